// round 2
// baseline (speedup 1.0000x reference)
#include <cuda_runtime.h>

#define BB 8192
#define TT 512
#define KK 12
#define GPB 32                     // batches (groups) per forward block
#define FWD_THREADS (GPB * KK)     // 384
#define BT_THREADS 128

// Scratch: trellis values best[b][t][k] (f32). 8192*512*12*4 = 201MB.
__device__ float g_trellis[(size_t)BB * TT * KK];
// Fallback scratch if the output buffer only holds one of the two results.
__device__ float g_scores_scratch[BB];
__device__ float g_paths_scratch[1];  // unused sink (never indexed beyond 0 in valid configs)

// ---------------------------------------------------------------------------
// Forward: lanes = tags (12 per batch group), 32 groups per block.
// Double-buffered smem exchange, one barrier per step. Stores f32 trellis.
// ---------------------------------------------------------------------------
__global__ __launch_bounds__(FWD_THREADS) void viterbi_fwd(
    const float* __restrict__ logits,   // [B, T, K]
    const float* __restrict__ trans)    // [K, K], trans[i*K+j] = i -> j
{
    __shared__ __align__(16) float buf[2][GPB][20];  // 20-float stride: 16B-aligned, bank-spread

    const int tid = threadIdx.x;
    const int g = tid / KK;
    const int j = tid - g * KK;
    const size_t b = (size_t)blockIdx.x * GPB + g;

    // Transition column j in registers: tc[i] = trans[i][j]
    float tc[KK];
#pragma unroll
    for (int i = 0; i < KK; i++) tc[i] = __ldg(trans + i * KK + j);

    const float* em = logits + b * TT * KK + j;
    float* tr = g_trellis + b * TT * KK + j;

    // t = 0: trellis row is just the emission
    float best = __ldcs(em);
    buf[0][g][j] = best;
    __stcs(tr, best);

#pragma unroll 2
    for (int t = 1; t < TT; t++) {
        const int p = (t - 1) & 1;
        __syncthreads();
        float4 a0 = *(const float4*)&buf[p][g][0];
        float4 a1 = *(const float4*)&buf[p][g][4];
        float4 a2 = *(const float4*)&buf[p][g][8];

        float v0  = a0.x + tc[0],  v1  = a0.y + tc[1];
        float v2  = a0.z + tc[2],  v3  = a0.w + tc[3];
        float v4  = a1.x + tc[4],  v5  = a1.y + tc[5];
        float v6  = a1.z + tc[6],  v7  = a1.w + tc[7];
        float v8  = a2.x + tc[8],  v9  = a2.y + tc[9];
        float v10 = a2.z + tc[10], v11 = a2.w + tc[11];

        float m = fmaxf(
            fmaxf(fmaxf(fmaxf(v0, v1), fmaxf(v2, v3)),
                  fmaxf(fmaxf(v4, v5), fmaxf(v6, v7))),
            fmaxf(fmaxf(v8, v9), fmaxf(v10, v11)));

        best = m + __ldcs(em + t * KK);
        buf[p ^ 1][g][j] = best;
        __stcs(tr + t * KK, best);
    }
}

// ---------------------------------------------------------------------------
// Tournament argmax over 12 values, first-index wins ties (matches jnp.argmax).
// Left operand of every merge covers strictly smaller indices, and >= keeps left.
// ---------------------------------------------------------------------------
__device__ __forceinline__ void sel2(float a, int ia, float b, int ib,
                                     float& ov, int& oi) {
    bool p = (a >= b);
    ov = p ? a : b;
    oi = p ? ia : ib;
}

__device__ __forceinline__ void amax12(const float* v, float& bv, int& bi) {
    float s0, s1, s2, s3, s4, s5;
    int   i0, i1, i2, i3, i4, i5;
    sel2(v[0],  0,  v[1],  1,  s0, i0);
    sel2(v[2],  2,  v[3],  3,  s1, i1);
    sel2(v[4],  4,  v[5],  5,  s2, i2);
    sel2(v[6],  6,  v[7],  7,  s3, i3);
    sel2(v[8],  8,  v[9],  9,  s4, i4);
    sel2(v[10], 10, v[11], 11, s5, i5);
    float t0, t1, t2; int k0, k1, k2;
    sel2(s0, i0, s1, i1, t0, k0);
    sel2(s2, i2, s3, i3, t1, k1);
    sel2(s4, i4, s5, i5, t2, k2);
    float u; int ku;
    sel2(t0, k0, t1, k1, u, ku);
    sel2(u, ku, t2, k2, bv, bi);
}

// ---------------------------------------------------------------------------
// Backtrace: one thread per batch. Recomputes argmax from stored trellis:
//   path[t] = argmax_i( trellis[b,t,i] + trans[i, path[t+1]] )
// Trellis rows are streamed backwards (addresses independent of the tag chain).
// ---------------------------------------------------------------------------
__global__ __launch_bounds__(BT_THREADS) void viterbi_btr(
    const float* __restrict__ trans,
    float* __restrict__ scores,   // [B]
    float* __restrict__ paths)    // [B, T] as float
{
    __shared__ __align__(16) float transT[KK * KK];  // transT[j*12+i] = trans[i][j]
    for (int idx = threadIdx.x; idx < KK * KK; idx += BT_THREADS) {
        int i = idx / KK, j = idx - i * KK;
        transT[j * KK + i] = trans[idx];
    }
    __syncthreads();

    const size_t b = (size_t)blockIdx.x * BT_THREADS + threadIdx.x;
    const float* tr = g_trellis + b * TT * KK;
    float* po = paths + b * TT;

    // Final row: score + last tag
    float v[12];
    {
        const float4* row = (const float4*)(tr + (size_t)(TT - 1) * KK);
        float4 r0 = __ldg(&row[0]), r1 = __ldg(&row[1]), r2 = __ldg(&row[2]);
        v[0] = r0.x; v[1] = r0.y; v[2]  = r0.z; v[3]  = r0.w;
        v[4] = r1.x; v[5] = r1.y; v[6]  = r1.z; v[7]  = r1.w;
        v[8] = r2.x; v[9] = r2.y; v[10] = r2.z; v[11] = r2.w;
    }
    float bv; int cur;
    amax12(v, bv, cur);
    scores[b] = bv;
    po[TT - 1] = (float)cur;

    // Prefetch row T-2, then walk backwards.
    float4 n0, n1, n2;
    {
        const float4* row = (const float4*)(tr + (size_t)(TT - 2) * KK);
        n0 = __ldg(&row[0]); n1 = __ldg(&row[1]); n2 = __ldg(&row[2]);
    }

#pragma unroll 2
    for (int t = TT - 2; t >= 0; --t) {
        float4 r0 = n0, r1 = n1, r2 = n2;
        if (t > 0) {
            const float4* row = (const float4*)(tr + (size_t)(t - 1) * KK);
            n0 = __ldg(&row[0]); n1 = __ldg(&row[1]); n2 = __ldg(&row[2]);
        }
        const float4* tc = (const float4*)(transT + cur * KK);
        float4 c0 = tc[0], c1 = tc[1], c2 = tc[2];

        float w[12];
        w[0] = r0.x + c0.x; w[1] = r0.y + c0.y; w[2]  = r0.z + c0.z; w[3]  = r0.w + c0.w;
        w[4] = r1.x + c1.x; w[5] = r1.y + c1.y; w[6]  = r1.z + c1.z; w[7]  = r1.w + c1.w;
        w[8] = r2.x + c2.x; w[9] = r2.y + c2.y; w[10] = r2.z + c2.z; w[11] = r2.w + c2.w;

        float mv; int mi;
        amax12(w, mv, mi);
        cur = mi;
        po[t] = (float)cur;
    }
}

// ---------------------------------------------------------------------------
// Launch
// ---------------------------------------------------------------------------
extern "C" void kernel_launch(void* const* d_in, const int* in_sizes, int n_in,
                              void* d_out, int out_size) {
    const float* logits = (const float*)d_in[0];
    const float* trans  = (const float*)d_in[1];
    // Robustness: if input order is swapped (trans is 144 elements), fix it.
    if (n_in >= 2 && in_sizes[0] == KK * KK) {
        const float* tmp = logits; logits = trans; trans = tmp;
    }

    viterbi_fwd<<<BB / GPB, FWD_THREADS>>>(logits, trans);

    float* out = (float*)d_out;
    float* scores;
    float* paths;
    float* d_scores_scratch = nullptr;
    cudaGetSymbolAddress((void**)&d_scores_scratch, g_scores_scratch);

    if (out_size >= BB * TT + BB) {
        // [scores (B) | paths (B*T)] flattened, concat order of the tuple
        scores = out;
        paths = out + BB;
    } else if (out_size == BB * TT) {
        // paths only
        scores = d_scores_scratch;
        paths = out;
    } else {
        // scores only (paths go to trellis head as a sink; harmless overwrite
        // of scratch that is no longer needed after this kernel)
        scores = out;
        float* d_tr = nullptr;
        cudaGetSymbolAddress((void**)&d_tr, g_trellis);
        paths = d_tr;  // g_trellis is large enough and dead after backtrace
    }

    viterbi_btr<<<BB / BT_THREADS, BT_THREADS>>>(trans, scores, paths);
}

// round 3
// speedup vs baseline: 2.4750x; 2.4750x over previous
#include <cuda_runtime.h>

#define BB 8192
#define TT 512
#define KK 12
#define GPB 16                       // batches per forward block
#define FWD_THREADS (GPB * 6)        // 6 threads per batch (2 tags each) = 96
#define BT_THREADS 32

// Packed backpointers: row (t,b) = u64, nibble j = best prev tag for tag j at t.
// Layout [T][B] -> forward writes coalesced bytes, backtrace reads coalesced u64.
__device__ unsigned long long g_bp[(size_t)TT * BB];   // 33.5 MB
// Final trellis row (t = T-1) values, [B][12] floats.
__device__ float g_final[(size_t)BB * KK];
// Fallback scratch if the output buffer only holds one of the two results.
__device__ float g_scores_scratch[BB];

// ---------------------------------------------------------------------------
// Combined max+argmax tournament, first-index wins ties (matches jnp.argmax):
// left operand of every merge covers strictly smaller indices; >= keeps left.
// ---------------------------------------------------------------------------
__device__ __forceinline__ void sel2(float a, int ia, float b, int ib,
                                     float& ov, int& oi) {
    bool p = (a >= b);
    ov = p ? a : b;
    oi = p ? ia : ib;
}

__device__ __forceinline__ void amax12(const float* v, float& bv, int& bi) {
    float s0, s1, s2, s3, s4, s5;
    int   i0, i1, i2, i3, i4, i5;
    sel2(v[0],  0,  v[1],  1,  s0, i0);
    sel2(v[2],  2,  v[3],  3,  s1, i1);
    sel2(v[4],  4,  v[5],  5,  s2, i2);
    sel2(v[6],  6,  v[7],  7,  s3, i3);
    sel2(v[8],  8,  v[9],  9,  s4, i4);
    sel2(v[10], 10, v[11], 11, s5, i5);
    float t0, t1, t2; int k0, k1, k2;
    sel2(s0, i0, s1, i1, t0, k0);
    sel2(s2, i2, s3, i3, t1, k1);
    sel2(s4, i4, s5, i5, t2, k2);
    float u; int ku;
    sel2(t0, k0, t1, k1, u, ku);
    sel2(u, ku, t2, k2, bv, bi);
}

// ---------------------------------------------------------------------------
// Forward: 6 threads per batch, thread k owns tags j0=2k, j1=2k+1.
// Per step: smem exchange of the 12 prev values (double-buffered, one barrier),
// 2x (12 FADD + combined max/argmax), packed bp byte to global.
// ---------------------------------------------------------------------------
__global__ __launch_bounds__(FWD_THREADS) void viterbi_fwd(
    const float* __restrict__ logits,   // [B, T, K]
    const float* __restrict__ trans)    // [K, K], trans[i*K+j] = i -> j
{
    __shared__ __align__(16) float buf[2][GPB][20];  // 80B row stride, 16B aligned

    const int tid = threadIdx.x;
    const int g = tid / 6;
    const int k = tid - g * 6;
    const size_t b = (size_t)blockIdx.x * GPB + g;
    const int j0 = 2 * k;

    // Two transition columns in registers: tc0[i] = trans[i][j0], tc1[i] = trans[i][j0+1]
    float tc0[KK], tc1[KK];
#pragma unroll
    for (int i = 0; i < KK; i++) {
        tc0[i] = __ldg(trans + i * KK + j0);
        tc1[i] = __ldg(trans + i * KK + j0 + 1);
    }

    const float* em = logits + b * TT * KK;
    unsigned char* bp8 = (unsigned char*)g_bp;

    // t = 0: prev row = emissions
    float2 e = *(const float2*)(em + j0);
    *(float2*)(&buf[0][g][j0]) = e;

    // prefetch emissions for t = 1
    float2 en = __ldg((const float2*)(em + KK + j0));

    float best0 = 0.f, best1 = 0.f;

#pragma unroll 2
    for (int t = 1; t < TT; t++) {
        __syncthreads();
        const float* r = &buf[(t - 1) & 1][g][0];
        float4 p0 = *(const float4*)(r);
        float4 p1 = *(const float4*)(r + 4);
        float4 p2 = *(const float4*)(r + 8);

        const float e0 = en.x, e1 = en.y;
        const int tn = (t + 1 < TT) ? (t + 1) : t;      // clamp final prefetch
        en = __ldg((const float2*)(em + (size_t)tn * KK + j0));

        float pv[12] = {p0.x, p0.y, p0.z, p0.w,
                        p1.x, p1.y, p1.z, p1.w,
                        p2.x, p2.y, p2.z, p2.w};
        float v0[12], v1[12];
#pragma unroll
        for (int i = 0; i < KK; i++) {
            v0[i] = pv[i] + tc0[i];
            v1[i] = pv[i] + tc1[i];
        }
        float m0, m1; int a0, a1;
        amax12(v0, m0, a0);
        amax12(v1, m1, a1);

        best0 = m0 + e0;
        best1 = m1 + e1;
        *(float2*)(&buf[t & 1][g][j0]) = make_float2(best0, best1);

        bp8[((size_t)t * BB + b) * 8 + k] = (unsigned char)(a0 | (a1 << 4));
    }

    // final trellis row for scores / last tag
    *(float2*)(g_final + b * KK + j0) = make_float2(best0, best1);
}

// ---------------------------------------------------------------------------
// Backtrace: one thread per batch. Nibble-extract walk over packed bp rows,
// software-pipelined loads in groups of 16 (addresses independent of the chain).
// Paths buffered 4-wide in registers -> STG.128.
// ---------------------------------------------------------------------------
__global__ __launch_bounds__(BT_THREADS) void viterbi_btr(
    float* __restrict__ scores,   // [B]
    float* __restrict__ paths)    // [B, T] as float
{
    const size_t b = (size_t)blockIdx.x * BT_THREADS + threadIdx.x;

    // score + last tag from the final trellis row
    float v[12];
    {
        const float4* row = (const float4*)(g_final + b * KK);
        float4 r0 = __ldg(&row[0]), r1 = __ldg(&row[1]), r2 = __ldg(&row[2]);
        v[0] = r0.x; v[1] = r0.y; v[2]  = r0.z; v[3]  = r0.w;
        v[4] = r1.x; v[5] = r1.y; v[6]  = r1.z; v[7]  = r1.w;
        v[8] = r2.x; v[9] = r2.y; v[10] = r2.z; v[11] = r2.w;
    }
    float bv; int cur;
    amax12(v, bv, cur);
    scores[b] = bv;

    float* po = paths + b * TT;
    float pbuf[4];
    pbuf[3] = (float)cur;   // path[T-1]

    const unsigned long long* bp = g_bp;

    unsigned long long r[16], rn[16];
    int t = TT - 1;   // 511
#pragma unroll
    for (int i = 0; i < 16; i++)
        r[i] = __ldg(bp + (size_t)(t - i) * BB + b);

    // 31 groups of 16 (t = 511..16), then tail of 15 (t = 15..1)
    for (int grp = 0; grp < 31; grp++) {
#pragma unroll
        for (int i = 0; i < 16; i++) {
            int tl = t - 16 - i;          // >= 0 always (row 0 exists, unused data ok)
            rn[i] = __ldg(bp + (size_t)tl * BB + b);
        }
#pragma unroll
        for (int i = 0; i < 16; i++) {
            const int tt = t - i;
            const int nx = (int)((r[i] >> (cur * 4)) & 15ull);
            pbuf[(tt - 1) & 3] = (float)nx;
            if (((tt - 1) & 3) == 0)
                *(float4*)(po + (tt - 1)) = make_float4(pbuf[0], pbuf[1], pbuf[2], pbuf[3]);
            cur = nx;
        }
#pragma unroll
        for (int i = 0; i < 16; i++) r[i] = rn[i];
        t -= 16;
    }
    // tail: t == 15, steps for tt = 15..1 (r[0..14] valid)
#pragma unroll
    for (int i = 0; i < 15; i++) {
        const int tt = 15 - i;
        const int nx = (int)((r[i] >> (cur * 4)) & 15ull);
        pbuf[(tt - 1) & 3] = (float)nx;
        if (((tt - 1) & 3) == 0)
            *(float4*)(po + (tt - 1)) = make_float4(pbuf[0], pbuf[1], pbuf[2], pbuf[3]);
        cur = nx;
    }
}

// ---------------------------------------------------------------------------
// Launch
// ---------------------------------------------------------------------------
extern "C" void kernel_launch(void* const* d_in, const int* in_sizes, int n_in,
                              void* d_out, int out_size) {
    const float* logits = (const float*)d_in[0];
    const float* trans  = (const float*)d_in[1];
    if (n_in >= 2 && in_sizes[0] == KK * KK) {  // robustness: swapped inputs
        const float* tmp = logits; logits = trans; trans = tmp;
    }

    viterbi_fwd<<<BB / GPB, FWD_THREADS>>>(logits, trans);

    float* out = (float*)d_out;
    float* scores;
    float* paths;
    float* d_scores_scratch = nullptr;
    cudaGetSymbolAddress((void**)&d_scores_scratch, g_scores_scratch);

    if (out_size >= BB * TT + BB) {
        scores = out;            // [scores (B) | paths (B*T)]
        paths = out + BB;
    } else if (out_size == BB * TT) {
        scores = d_scores_scratch;
        paths = out;
    } else {
        scores = out;
        float* d_bp = nullptr;
        cudaGetSymbolAddress((void**)&d_bp, g_bp);
        paths = (float*)d_bp;    // dead scratch as sink
    }

    viterbi_btr<<<BB / BT_THREADS, BT_THREADS>>>(scores, paths);
}